// round 16
// baseline (speedup 1.0000x reference)
#include <cuda_runtime.h>
#include <cuda.h>
#include <math.h>
#include <string.h>

#define BB 8
#define LL 8192
#define DD 768
#define NE 128
#define NPAIR (NE*(NE-1)/2)   // 8128 = 16*508
#define NP4   (DD/4)          // 192
#define KSPLIT 16
#define KC     (DD/KSPLIT)    // 48
#define KC4    (KC/4)         // 12
#define PITCH  132
#define NTILE  272            // 8x4 tiles, tx >= 2*ty
#define TPB    512

#define SPAN_FLTS 768                   // 16 rows x 48 floats per staged span
#define WAVE_FLTS (16*SPAN_FLTS)        // 12288 floats = 49152 B
#define NBUF  3
#define SMEM_DYN ((KC*PITCH + NBUF*WAVE_FLTS) * 4)   // 25344 + 147456 = 172800 B

typedef unsigned long long ull;

// Scratch (no allocations allowed)
__device__ float  g_par[KSPLIT][BB*NE*NE]; // raw gram partials (upper tiles; lower stays 0)
__device__ float  g_sim[BB*NE*NE];         // summed normalized sims
__device__ double g_qs[BB][KSPLIT][2];     // per-band fp64 {sum,sumsq}
__device__ float  g_cinv[BB];              // 1/(std+1e-5)
// counters: all return to 0 every launch (replay-safe)
__device__ int g_simcnt[BB];
__device__ int g_sobs[BB];
__device__ int g_scnt[BB];
__device__ int g_ready[BB];
__device__ int g_rcnt[BB];

// ---- acq/rel primitives ---------------------------------------------------
__device__ __forceinline__ void red_add_release(int* p, int v) {
    asm volatile("red.release.gpu.global.add.s32 [%0], %1;"
                 :: "l"(p), "r"(v) : "memory");
}
__device__ __forceinline__ int atom_add_acqrel(int* p, int v) {
    int r;
    asm volatile("atom.acq_rel.gpu.global.add.s32 %0, [%1], %2;"
                 : "=r"(r) : "l"(p), "r"(v) : "memory");
    return r;
}
__device__ __forceinline__ int ld_acquire(const int* p) {
    int r;
    asm volatile("ld.acquire.gpu.global.s32 %0, [%1];"
                 : "=r"(r) : "l"(p) : "memory");
    return r;
}
__device__ __forceinline__ void st_release(int* p, int v) {
    asm volatile("st.release.gpu.global.s32 [%0], %1;"
                 :: "l"(p), "r"(v) : "memory");
}

// ---- mbarrier + TMA helpers -----------------------------------------------
__device__ __forceinline__ void mbar_init(unsigned a, unsigned cnt) {
    asm volatile("mbarrier.init.shared.b64 [%0], %1;" :: "r"(a), "r"(cnt) : "memory");
}
__device__ __forceinline__ void mbar_expect(unsigned a, unsigned bytes) {
    asm volatile("mbarrier.arrive.expect_tx.shared.b64 _, [%0], %1;"
                 :: "r"(a), "r"(bytes) : "memory");
}
__device__ __forceinline__ void mbar_wait(unsigned a, unsigned ph) {
    asm volatile(
        "{\n\t.reg .pred P;\n\t"
        "WL%=:\n\t"
        "mbarrier.try_wait.parity.acquire.cta.shared::cta.b64 P, [%0], %1, 0x989680;\n\t"
        "@P bra WD%=;\n\t"
        "bra WL%=;\n\t"
        "WD%=:\n\t}"
        :: "r"(a), "r"(ph) : "memory");
}
__device__ __forceinline__ void tma2d(unsigned dst, const CUtensorMap* m,
                                      int c0, int c1, unsigned mb) {
    asm volatile(
        "cp.async.bulk.tensor.2d.shared::cta.global.tile.mbarrier::complete_tx::bytes "
        "[%0], [%1, {%2, %3}], [%4];"
        :: "r"(dst), "l"(m), "r"(c0), "r"(c1), "r"(mb) : "memory");
}

// ---- packed f32x2 helpers ------------------------------------------------
__device__ __forceinline__ void fma2(ull &d, ull a, ull b) {
    asm("fma.rn.f32x2 %0, %1, %2, %0;" : "+l"(d) : "l"(a), "l"(b));
}
__device__ __forceinline__ ull pack2(float v) {
    ull r; unsigned u = __float_as_uint(v);
    asm("mov.b64 %0, {%1, %1};" : "=l"(r) : "r"(u));
    return r;
}
__device__ __forceinline__ void unpack2(ull v, float &lo, float &hi) {
    unsigned a, b;
    asm("mov.b64 {%0, %1}, %2;" : "=r"(a), "=r"(b) : "l"(v));
    lo = __uint_as_float(a); hi = __uint_as_float(b);
}

// ---------------------------------------------------------------------------
__global__ void __launch_bounds__(TPB, 1)
k_all(const __grid_constant__ CUtensorMap tmap,
      int use_tma,
      const float* __restrict__ x,
      const int*   __restrict__ starts,
      const int*   __restrict__ lengths,
      const int*   __restrict__ hts,
      const float* __restrict__ thr,
      const float* __restrict__ W1,
      const float* __restrict__ b1,
      const float* __restrict__ W2,
      const float* __restrict__ b2,
      float*       __restrict__ out) {
    const int blk = blockIdx.x;           // 0..127
    const int b   = blk >> 4;             // batch
    const int kc  = blk & 15;             // k-chunk == band id == pair-chunk id
    const int tid = threadIdx.x;          // 512
    const int w   = tid >> 5;
    const int lane = tid & 31;

    extern __shared__ __align__(128) float dyn[];
    float (*At)[PITCH] = reinterpret_cast<float (*)[PITCH]>(dyn);  // 48x132
    float* stage = dyn + KC*PITCH;

    __shared__ ull    mbars[NBUF];
    __shared__ int    sSt[NE], sLn[NE];
    __shared__ float  sRi[NE];
    __shared__ float  r0[128], r1[128], r2[128], r3[128];
    __shared__ int    rf[128];
    __shared__ double sS16[16], sQ16[16];

    // ======= Phase A: gather-pool 48-float slice of 128 spans ==============
    if (tid < NE) {
        sSt[tid] = starts[b*NE + tid];
        sLn[tid] = lengths[b*NE + tid];
    }
    if (tid == 0)
        for (int i = 0; i < NBUF; ++i)
            mbar_init((unsigned)__cvta_generic_to_shared(&mbars[i]), 1u);
    __syncthreads();

    if (use_tma) {
        const unsigned stage_u32 = (unsigned)__cvta_generic_to_shared(stage);
        // ---- TMA pipelined: 8 waves x 16 spans, 3 buffers ----
        auto issue_wave = [&](int wv) {
            const int buf = wv % NBUF;
            const unsigned mb = (unsigned)__cvta_generic_to_shared(&mbars[buf]);
            unsigned bytes = 0;
            #pragma unroll
            for (int i = 0; i < 16; ++i)
                bytes += (sLn[wv*16 + i] > 8) ? 3072u : 1536u;
            mbar_expect(mb, bytes);
            #pragma unroll
            for (int i = 0; i < 16; ++i) {
                const int sp  = wv*16 + i;
                const int row = b*LL + sSt[sp];
                const unsigned dst = stage_u32 + (unsigned)(buf*WAVE_FLTS + i*SPAN_FLTS)*4u;
                tma2d(dst, &tmap, kc*KC, row, mb);
                if (sLn[sp] > 8) tma2d(dst + 1536u, &tmap, kc*KC, row + 8, mb);
            }
        };
        if (tid == 0) { issue_wave(0); issue_wave(1); issue_wave(2); }

        #pragma unroll 1
        for (int wv = 0; wv < 8; ++wv) {
            const int buf = wv % NBUF;
            mbar_wait((unsigned)__cvta_generic_to_shared(&mbars[buf]),
                      (unsigned)((wv / NBUF) & 1));
            // warp w reduces span wv*16+w; 12 lanes each own one f4 column
            if (lane < 12) {
                const int sp  = wv*16 + w;
                const int len = sLn[sp];          // warp-uniform
                const float4* rowp = (const float4*)(stage + buf*WAVE_FLTS + w*SPAN_FLTS) + lane;
                float4 a = make_float4(0.f, 0.f, 0.f, 0.f);
                for (int t = 0; t < len; ++t) {
                    const float4 v = rowp[t*12];
                    a.x += v.x; a.y += v.y; a.z += v.z; a.w += v.w;
                }
                const float il = 1.0f / (float)len;
                At[4*lane+0][sp] = a.x*il;
                At[4*lane+1][sp] = a.y*il;
                At[4*lane+2][sp] = a.z*il;
                At[4*lane+3][sp] = a.w*il;
            }
            __syncthreads();                      // buffer drained
            if (tid == 0 && wv + NBUF < 8) issue_wave(wv + NBUF);
        }
    } else {
        // ---- fallback: R15 LDG gather-pool ----
        const int grp = tid >> 4;
        const int c   = tid & 15;
        if (c < 12) {
            const float4* xb4 = (const float4*)x + (long)b*LL*NP4 + kc*KC4 + c;
            const int sp0 = grp,      sp1 = grp + 32;
            const int sp2 = grp + 64, sp3 = grp + 96;
            const int l0 = sLn[sp0], l1 = sLn[sp1], l2 = sLn[sp2], l3 = sLn[sp3];
            const float4* p0 = xb4 + (long)sSt[sp0]*NP4;
            const float4* p1 = xb4 + (long)sSt[sp1]*NP4;
            const float4* p2 = xb4 + (long)sSt[sp2]*NP4;
            const float4* p3 = xb4 + (long)sSt[sp3]*NP4;
            float4 a0 = make_float4(0,0,0,0), a1 = a0, a2 = a0, a3 = a0;
            #pragma unroll
            for (int t = 0; t < 16; ++t) {
                if (t < l0) { const float4 v = __ldcs(p0 + (long)t*NP4); a0.x+=v.x; a0.y+=v.y; a0.z+=v.z; a0.w+=v.w; }
                if (t < l1) { const float4 v = __ldcs(p1 + (long)t*NP4); a1.x+=v.x; a1.y+=v.y; a1.z+=v.z; a1.w+=v.w; }
                if (t < l2) { const float4 v = __ldcs(p2 + (long)t*NP4); a2.x+=v.x; a2.y+=v.y; a2.z+=v.z; a2.w+=v.w; }
                if (t < l3) { const float4 v = __ldcs(p3 + (long)t*NP4); a3.x+=v.x; a3.y+=v.y; a3.z+=v.z; a3.w+=v.w; }
            }
            const float i0 = 1.0f/(float)l0, i1 = 1.0f/(float)l1;
            const float i2 = 1.0f/(float)l2, i3 = 1.0f/(float)l3;
            At[4*c+0][sp0] = a0.x*i0; At[4*c+1][sp0] = a0.y*i0;
            At[4*c+2][sp0] = a0.z*i0; At[4*c+3][sp0] = a0.w*i0;
            At[4*c+0][sp1] = a1.x*i1; At[4*c+1][sp1] = a1.y*i1;
            At[4*c+2][sp1] = a1.z*i1; At[4*c+3][sp1] = a1.w*i1;
            At[4*c+0][sp2] = a2.x*i2; At[4*c+1][sp2] = a2.y*i2;
            At[4*c+2][sp2] = a2.z*i2; At[4*c+3][sp2] = a2.w*i2;
            At[4*c+0][sp3] = a3.x*i3; At[4*c+1][sp3] = a3.y*i3;
            At[4*c+2][sp3] = a3.z*i3; At[4*c+3][sp3] = a3.w*i3;
        }
    }
    __syncthreads();

    // ======= Phase B: upper-triangular FFMA2 syrk (8x4 tiles, 272 thr) =====
    if (tid < NTILE) {
        int ty = 0, off = 0;
        #pragma unroll
        for (int y = 0; y < 15; ++y) {
            const int cnt = 32 - 2*ty;
            if (tid - off >= cnt) { off += cnt; ty++; }
        }
        const int tx = 2*ty + (tid - off);
        const int i8 = ty*8, j4 = tx*4;

        ull c[8][2];
        #pragma unroll
        for (int r = 0; r < 8; ++r) { c[r][0] = 0ull; c[r][1] = 0ull; }

        #pragma unroll 4
        for (int kk = 0; kk < KC; ++kk) {
            const float4 alo = *(const float4*)&At[kk][i8];
            const float4 ahi = *(const float4*)&At[kk][i8 + 4];
            ull a2[8];
            a2[0]=pack2(alo.x); a2[1]=pack2(alo.y); a2[2]=pack2(alo.z); a2[3]=pack2(alo.w);
            a2[4]=pack2(ahi.x); a2[5]=pack2(ahi.y); a2[6]=pack2(ahi.z); a2[7]=pack2(ahi.w);
            const ulonglong2 bv = *(const ulonglong2*)&At[kk][j4];
            #pragma unroll
            for (int r = 0; r < 8; ++r) {
                fma2(c[r][0], a2[r], bv.x);
                fma2(c[r][1], a2[r], bv.y);
            }
        }

        float* P = g_par[kc] + (long)b*NE*NE + i8*NE + j4;
        #pragma unroll
        for (int r = 0; r < 8; ++r) {
            float l0,h0,l1,h1;
            unpack2(c[r][0], l0, h0);
            unpack2(c[r][1], l1, h1);
            __stcg((float4*)(P + (long)r*NE), make_float4(l0, h0, l1, h1));
        }
    }
    __syncthreads();
    if (tid == 0) red_add_release(&g_simcnt[b], 1);

    // ======= Phase C: MLP collapse (input-only) ============================
    if (tid < 128) {
        const float w1  = W1[tid];
        const float w20 = W2[2*tid], w21 = W2[2*tid+1];
        r0[tid] = (w1 > 0.f) ? w1*w20 : 0.f;
        r1[tid] = (w1 > 0.f) ? w1*w21 : 0.f;
        r2[tid] = (w1 < 0.f) ? w1*w20 : 0.f;
        r3[tid] = (w1 < 0.f) ? w1*w21 : 0.f;
        rf[tid] = (b1[tid] != 0.f) ? 1 : 0;
    }
    __syncthreads();
    #pragma unroll
    for (int o = 64; o > 0; o >>= 1) {
        if (tid < o) {
            r0[tid]+=r0[tid+o]; r1[tid]+=r1[tid+o];
            r2[tid]+=r2[tid+o]; r3[tid]+=r3[tid+o];
            rf[tid]|=rf[tid+o];
        }
        __syncthreads();
    }

    // ---- wait for all 16 syrk chunk blocks of this batch ----
    if (tid == 0) {
        while (ld_acquire(&g_simcnt[b]) < KSPLIT) __nanosleep(32);
        const int a = atom_add_acqrel(&g_sobs[b], 1);
        if (a == KSPLIT - 1) { g_sobs[b] = 0; g_simcnt[b] = 0; }
    }
    __syncthreads();

    // ---- all 128 diagonal norms locally (L2 hits) ----
    if (tid < NE) {
        const float* D = g_par[0] + (long)b*NE*NE + (long)tid*(NE+1);
        float d = 0.f;
        #pragma unroll
        for (int k2 = 0; k2 < KSPLIT; ++k2)
            d += __ldcg(D + (long)k2*(BB*NE*NE));
        sRi[tid] = rsqrtf(fmaxf(d, 1e-16f));
    }
    __syncthreads();

    // ======= Phase D: band sum + normalize + stats =========================
    float s = 0.f, qq = 0.f;
    if (tid < 256) {
        const int f  = kc*256 + tid;
        const int i  = f >> 5;
        const int j0 = (f & 31) * 4;
        float4 a = make_float4(0.f,0.f,0.f,0.f);
        #pragma unroll
        for (int k2 = 0; k2 < KSPLIT; ++k2) {
            const float4 v = __ldcg(&((const float4*)(g_par[k2] + (long)b*NE*NE))[f]);
            a.x+=v.x; a.y+=v.y; a.z+=v.z; a.w+=v.w;
        }
        const float ri = sRi[i];
        a.x *= ri * sRi[j0  ];
        a.y *= ri * sRi[j0+1];
        a.z *= ri * sRi[j0+2];
        a.w *= ri * sRi[j0+3];
        __stcg(&((float4*)(g_sim + (long)b*NE*NE))[f], a);
        const float wx = (j0   > i) ? 2.f : (j0   == i) ? 1.f : 0.f;
        const float wy = (j0+1 > i) ? 2.f : (j0+1 == i) ? 1.f : 0.f;
        const float wz = (j0+2 > i) ? 2.f : (j0+2 == i) ? 1.f : 0.f;
        const float ww = (j0+3 > i) ? 2.f : (j0+3 == i) ? 1.f : 0.f;
        s  += wx*a.x + wy*a.y + wz*a.z + ww*a.w;
        qq += wx*a.x*a.x + wy*a.y*a.y + wz*a.z*a.z + ww*a.w*a.w;
    }
    double ds = (double)s, dq = (double)qq;
    #pragma unroll
    for (int o = 16; o > 0; o >>= 1) {
        ds += __shfl_xor_sync(0xffffffffu, ds, o);
        dq += __shfl_xor_sync(0xffffffffu, dq, o);
    }
    if (lane == 0) { sS16[w] = ds; sQ16[w] = dq; }
    __syncthreads();
    if (tid == 0) {
        double ts = 0.0, tq = 0.0;
        #pragma unroll
        for (int w2 = 0; w2 < 16; ++w2) { ts += sS16[w2]; tq += sQ16[w2]; }
        g_qs[b][kc][0] = ts;
        g_qs[b][kc][1] = tq;
        const int a3 = atom_add_acqrel(&g_scnt[b], 1);
        if (a3 == KSPLIT - 1) {
            double fs = 0.0, fq = 0.0;
            #pragma unroll
            for (int q2 = 0; q2 < KSPLIT; ++q2) { fs += g_qs[b][q2][0]; fq += g_qs[b][q2][1]; }
            const double n  = (double)(NE*NE);
            const double sd = sqrt((fq - fs*fs/n) / (n - 1.0));
            g_cinv[b] = 1.0f / ((float)sd + 1e-5f);
            g_scnt[b] = 0;
            st_release(&g_ready[b], 1);
        }
        while (ld_acquire(&g_ready[b]) == 0) __nanosleep(32);
        const int a4 = atom_add_acqrel(&g_rcnt[b], 1);
        if (a4 == KSPLIT - 1) { g_rcnt[b] = 0; g_ready[b] = 0; }
    }
    __syncthreads();

    // ======= Phase E: classify 508 pairs (chunk kc of batch b) =============
    {
        const float cinv = __ldcg(&g_cinv[b]);
        const float t0   = __ldg(thr);
        const float b20  = __ldg(&b2[0]), b21 = __ldg(&b2[1]);

        if (tid < 508) {
            const int gp = b*NPAIR + kc*508 + tid;
            const int2 ht = ((const int2*)hts)[gp];
            const float sim = __ldcg(&g_sim[(long)b*NE*NE + ht.x*NE + ht.y]);
            const float pv  = (sim - t0) * cinv;
            float o0, o1;
            if (rf[0] == 0) {
                o0 = fmaf(pv, (pv > 0.f) ? r0[0] : r2[0], b20);
                o1 = fmaf(pv, (pv > 0.f) ? r1[0] : r3[0], b21);
            } else {
                o0 = b20; o1 = b21;
                #pragma unroll 8
                for (int k = 0; k < 128; ++k) {
                    const float h = fmaxf(fmaf(pv, __ldg(&W1[k]), __ldg(&b1[k])), 0.f);
                    o0 = fmaf(h, __ldg(&W2[2*k  ]), o0);
                    o1 = fmaf(h, __ldg(&W2[2*k+1]), o1);
                }
            }
            ((float2*)out)[gp] = make_float2(o0, o1);
        }
    }
}

// ---------------------------------------------------------------------------
typedef CUresult (*EncodeFn)(CUtensorMap*, CUtensorMapDataType, cuuint32_t, void*,
                             const cuuint64_t*, const cuuint64_t*, const cuuint32_t*,
                             const cuuint32_t*, CUtensorMapInterleave, CUtensorMapSwizzle,
                             CUtensorMapL2promotion, CUtensorMapFloatOOBfill);

extern "C" void kernel_launch(void* const* d_in, const int* in_sizes, int n_in,
                              void* d_out, int out_size) {
    const float* x       = (const float*)d_in[0];
    const int*   starts  = (const int*)  d_in[1];
    const int*   lengths = (const int*)  d_in[2];
    const int*   hts     = (const int*)  d_in[3];
    const float* thr     = (const float*)d_in[4];
    const float* W1      = (const float*)d_in[5];
    const float* b1      = (const float*)d_in[6];
    const float* W2      = (const float*)d_in[7];
    const float* b2      = (const float*)d_in[8];
    float* out = (float*)d_out;

    CUtensorMap tmap;
    memset(&tmap, 0, sizeof(tmap));
    int use_tma = 0;

    EncodeFn enc = nullptr;
    cudaDriverEntryPointQueryResult qr;
    if (cudaGetDriverEntryPoint("cuTensorMapEncodeTiled", (void**)&enc,
                                cudaEnableDefault, &qr) == cudaSuccess &&
        enc != nullptr) {
        cuuint64_t dims[2]    = {DD, (cuuint64_t)BB*LL};
        cuuint64_t strides[1] = {DD * sizeof(float)};
        cuuint32_t box[2]     = {KC, 8};
        cuuint32_t estr[2]    = {1, 1};
        if (enc(&tmap, CU_TENSOR_MAP_DATA_TYPE_FLOAT32, 2, (void*)x,
                dims, strides, box, estr,
                CU_TENSOR_MAP_INTERLEAVE_NONE, CU_TENSOR_MAP_SWIZZLE_NONE,
                CU_TENSOR_MAP_L2_PROMOTION_L2_128B,
                CU_TENSOR_MAP_FLOAT_OOB_FILL_NONE) == CUDA_SUCCESS)
            use_tma = 1;
    }

    cudaFuncSetAttribute(k_all, cudaFuncAttributeMaxDynamicSharedMemorySize, SMEM_DYN);
    k_all<<<BB*KSPLIT, TPB, SMEM_DYN>>>(tmap, use_tma, x, starts, lengths, hts,
                                        thr, W1, b1, W2, b2, out);
}